// round 1
// baseline (speedup 1.0000x reference)
#include <cuda_runtime.h>
#include <cuda_fp16.h>

#define BB 32
#define JJ 2048
#define II 16
#define NN 64
#define DD 32
#define SQ_EPS 1e-7f

// ---------------- device scratch (no allocations allowed) ----------------
__device__ __half g_uhat[(size_t)BB * JJ * NN * DD];   // [b][j][n][d], 268 MB
__device__ float  g_v[BB * NN * DD];                   // [b][n][d]
__device__ float  g_blog[(size_t)BB * JJ * NN];        // [b][j][n], 16 MB
__device__ float  g_sp[32 * BB * NN * DD];             // partial s slices, 8 MB

// ---------------- zero the routing logits ----------------
__global__ void k0_zero_blog() {
    size_t i = (size_t)blockIdx.x * blockDim.x + threadIdx.x;   // 4096*256 = 1,048,576 float4
    float4 z = make_float4(0.f, 0.f, 0.f, 0.f);
    ((float4*)g_blog)[i] = z;
}

// ---------------- K1: u_hat = einsum('bji,njdi') + partial sum_j u_hat ----------------
// grid = 64 n * 32 superchunks (64 j each), 256 threads
__global__ __launch_bounds__(256) void k1_uhat(const float* __restrict__ x,
                                               const float* __restrict__ W) {
    __shared__ float Ws[8 * 32 * 20];  // [j][d][i pad 20] -> conflict-free LDS.128
    __shared__ float xs[32 * 128];     // [b][(j*16+i)]

    int n  = blockIdx.x >> 5;
    int sc = blockIdx.x & 31;
    int t  = threadIdx.x;
    int w  = t >> 5;      // warp 0..7 -> base b
    int d  = t & 31;      // lane = output dim

    float sacc[4] = {0.f, 0.f, 0.f, 0.f};

    for (int sub = 0; sub < 8; sub++) {
        int j0 = sc * 64 + sub * 8;

        // load W tile: 8 j * 32 d * 16 i = 4096 floats = 1024 float4, transposed pad-20
        const float4* Wg = (const float4*)(W + ((size_t)n * JJ + j0) * DD * II);
        #pragma unroll
        for (int r = 0; r < 4; r++) {
            int idx = r * 256 + t;
            float4 v = Wg[idx];
            int q = idx & 3, dd = (idx >> 2) & 31, jj = idx >> 7;
            *(float4*)&Ws[(jj * 32 + dd) * 20 + q * 4] = v;
        }
        // load x tile: 32 b * (8 j * 16 i = 128 contiguous floats)
        #pragma unroll
        for (int r = 0; r < 4; r++) {
            int idx = r * 256 + t;
            int b = idx >> 5, rr = idx & 31;
            const float4* xg = (const float4*)(x + ((size_t)b * JJ + j0) * II);
            *(float4*)&xs[b * 128 + rr * 4] = xg[rr];
        }
        __syncthreads();

        #pragma unroll
        for (int j = 0; j < 8; j++) {
            const float* wrow = &Ws[(j * 32 + d) * 20];
            float4 wa = *(const float4*)(wrow);
            float4 wb = *(const float4*)(wrow + 4);
            float4 wc = *(const float4*)(wrow + 8);
            float4 wd = *(const float4*)(wrow + 12);
            int jg = j0 + j;
            #pragma unroll
            for (int k = 0; k < 4; k++) {
                int b = w + k * 8;
                const float* xrow = &xs[b * 128 + j * 16];   // broadcast across warp
                float4 xa = *(const float4*)(xrow);
                float4 xb = *(const float4*)(xrow + 4);
                float4 xc = *(const float4*)(xrow + 8);
                float4 xd = *(const float4*)(xrow + 12);
                float acc = wa.x * xa.x;
                acc = fmaf(wa.y, xa.y, acc); acc = fmaf(wa.z, xa.z, acc); acc = fmaf(wa.w, xa.w, acc);
                acc = fmaf(wb.x, xb.x, acc); acc = fmaf(wb.y, xb.y, acc);
                acc = fmaf(wb.z, xb.z, acc); acc = fmaf(wb.w, xb.w, acc);
                acc = fmaf(wc.x, xc.x, acc); acc = fmaf(wc.y, xc.y, acc);
                acc = fmaf(wc.z, xc.z, acc); acc = fmaf(wc.w, xc.w, acc);
                acc = fmaf(wd.x, xd.x, acc); acc = fmaf(wd.y, xd.y, acc);
                acc = fmaf(wd.z, xd.z, acc); acc = fmaf(wd.w, xd.w, acc);
                g_uhat[(((size_t)b * JJ + jg) * NN + n) * DD + d] = __float2half_rn(acc);
                sacc[k] += acc;
            }
        }
        __syncthreads();
    }
    // non-atomic partial: slice sc, value unique per (b,n,d)
    #pragma unroll
    for (int k = 0; k < 4; k++) {
        int b = w + k * 8;
        g_sp[(size_t)sc * (BB * NN * DD) + ((size_t)b * NN + n) * DD + d] = sacc[k];
    }
}

// ---------------- K2: reduce partial slices, squash, write v ----------------
// grid = 256 blocks * 256 threads; warp per (b,n)
__global__ __launch_bounds__(256) void k2_squash(int nslices, float prescale,
                                                 float* __restrict__ outp) {
    int g = blockIdx.x * 8 + (threadIdx.x >> 5);   // 0..2047 = b*64+n
    int l = threadIdx.x & 31;                      // lane = d
    float s = 0.f;
    for (int sl = 0; sl < nslices; sl++)
        s += g_sp[(size_t)sl * (BB * NN * DD) + (size_t)g * DD + l];
    s *= prescale;
    float sq = s * s;
    #pragma unroll
    for (int o = 16; o > 0; o >>= 1) sq += __shfl_xor_sync(0xffffffffu, sq, o);
    float scale = sq / ((1.f + sq) * sqrtf(sq + SQ_EPS));
    float* o = outp ? outp : g_v;
    o[(size_t)g * DD + l] = s * scale;
}

// ---------------- K3: fused routing pass ----------------
// b_new = b_old + v . u_hat ; c = softmax_n(b_new) ; s_partial += c * u_hat
// grid = 32 b * 16 chunkgroups (8 chunks of 16 j each), 512 threads (16 warps)
#define K3_SMEM ((16 * 2112 + 2112 + 1024) * 4)   // u_s + v_s + c_s = 147,712 B

__global__ __launch_bounds__(512) void k3_route() {
    extern __shared__ float sm[];
    float* u_s = sm;            // [16][64*33] padded
    float* v_s = sm + 16 * 2112;
    float* c_s = v_s + 2112;    // [16][64]

    int b  = blockIdx.x >> 4;
    int cg = blockIdx.x & 15;
    int t  = threadIdx.x;
    int w  = t >> 5;    // warp 0..15
    int l  = t & 31;

    // load v[b] once, padded stride 33
    {
        float4 vv = ((const float4*)(g_v + (size_t)b * NN * DD))[t];
        int p = t * 4;
        float* dst = &v_s[(p >> 5) * 33 + (p & 31)];
        dst[0] = vv.x; dst[1] = vv.y; dst[2] = vv.z; dst[3] = vv.w;
    }

    float acc0 = 0.f, acc1 = 0.f, acc2 = 0.f, acc3 = 0.f;   // persistent s-partials, n = 4w+nn

    for (int cc = 0; cc < 8; cc++) {
        int j0 = (cg * 8 + cc) * 16;
        __syncthreads();   // protect u_s/c_s from previous iteration's readers

        // load u tile: 16 j * 2048 halves, convert to fp32 padded
        const uint4* ug = (const uint4*)(g_uhat + ((size_t)b * JJ + j0) * NN * DD);
        #pragma unroll
        for (int r = 0; r < 8; r++) {
            int idx = r * 512 + t;            // 0..4095, 8 halves each
            uint4 pk = ug[idx];
            int p  = idx * 8;
            int j  = p >> 11, nn = (p >> 5) & 63, d0 = p & 31;
            float* dst = &u_s[j * 2112 + nn * 33 + d0];
            const __half2* hp = (const __half2*)&pk;
            #pragma unroll
            for (int q = 0; q < 4; q++) {
                float2 f = __half22float2(hp[q]);
                dst[2 * q] = f.x; dst[2 * q + 1] = f.y;
            }
        }
        __syncthreads();

        // B1: warp w handles j = j0 + w : logit update + softmax over n
        {
            int jg = j0 + w;
            const float* uj = &u_s[w * 2112];
            const float* v0p = &v_s[l * 33];
            const float* v1p = &v_s[(l + 32) * 33];
            const float* u0p = &uj[l * 33];
            const float* u1p = &uj[(l + 32) * 33];
            float t0 = 0.f, t1 = 0.f;
            #pragma unroll
            for (int dd = 0; dd < 32; dd++) {
                t0 = fmaf(v0p[dd], u0p[dd], t0);
                t1 = fmaf(v1p[dd], u1p[dd], t1);
            }
            float* bl = &g_blog[((size_t)b * JJ + jg) * NN];
            float b0 = bl[l] + t0;
            float b1 = bl[l + 32] + t1;
            bl[l] = b0; bl[l + 32] = b1;
            float m = fmaxf(b0, b1);
            #pragma unroll
            for (int o = 16; o > 0; o >>= 1) m = fmaxf(m, __shfl_xor_sync(0xffffffffu, m, o));
            float e0 = __expf(b0 - m), e1 = __expf(b1 - m);
            float ssum = e0 + e1;
            #pragma unroll
            for (int o = 16; o > 0; o >>= 1) ssum += __shfl_xor_sync(0xffffffffu, ssum, o);
            float inv = 1.0f / ssum;
            c_s[w * 64 + l]      = e0 * inv;
            c_s[w * 64 + 32 + l] = e1 * inv;
        }
        __syncthreads();

        // B2: warp w owns n in [4w, 4w+4); lane = d; accumulate over the 16 j in smem
        #pragma unroll
        for (int j = 0; j < 16; j++) {
            const float* uj = &u_s[j * 2112 + (4 * w) * 33];
            const float* cj = &c_s[j * 64 + 4 * w];
            acc0 = fmaf(cj[0], uj[0 * 33 + l], acc0);
            acc1 = fmaf(cj[1], uj[1 * 33 + l], acc1);
            acc2 = fmaf(cj[2], uj[2 * 33 + l], acc2);
            acc3 = fmaf(cj[3], uj[3 * 33 + l], acc3);
        }
    }

    // non-atomic partial write: slice cg, unique (b, n, d) per thread
    float* sp = &g_sp[(size_t)cg * (BB * NN * DD) + ((size_t)b * NN + 4 * w) * DD + l];
    sp[0 * DD] = acc0;
    sp[1 * DD] = acc1;
    sp[2 * DD] = acc2;
    sp[3 * DD] = acc3;
}

// ---------------- launch ----------------
extern "C" void kernel_launch(void* const* d_in, const int* in_sizes, int n_in,
                              void* d_out, int out_size) {
    const float* x = (const float*)d_in[0];
    const float* W = (const float*)d_in[1];
    if (n_in >= 2 && in_sizes[0] != BB * JJ * II) {   // defend against input ordering
        x = (const float*)d_in[1];
        W = (const float*)d_in[0];
    }
    float* out = (float*)d_out;

    cudaFuncSetAttribute(k3_route, cudaFuncAttributeMaxDynamicSharedMemorySize, K3_SMEM);

    k0_zero_blog<<<4096, 256>>>();                     // b logits = 0
    k1_uhat<<<2048, 256>>>(x, W);                      // u_hat (fp16) + raw sum_j partials
    k2_squash<<<256, 256>>>(32, 1.0f / NN, nullptr);   // v0 = squash(sum/64)
    k3_route<<<512, 512, K3_SMEM>>>();                 // b1, c1 = softmax(b1), s1 partials
    k2_squash<<<256, 256>>>(16, 1.0f, nullptr);        // v1
    k3_route<<<512, 512, K3_SMEM>>>();                 // b2, c2, s2 partials
    k2_squash<<<256, 256>>>(16, 1.0f, out);            // v2 -> output
}

// round 2
// speedup vs baseline: 1.2649x; 1.2649x over previous
#include <cuda_runtime.h>
#include <cuda_fp16.h>

#define BB 32
#define JJ 2048
#define II 16
#define NN 64
#define DD 32
#define SQ_EPS 1e-7f

// packed 2-wide fp32 FMA (sm_103a; only reachable via PTX)
#define FMA_F32X2(d, a, b, c) \
    asm("fma.rn.f32x2 %0, %1, %2, %3;" : "=l"(d) : "l"(a), "l"(b), "l"(c))
#define UNPACK_F32X2(lo, hi, in) \
    asm("mov.b64 {%0, %1}, %2;" : "=f"(lo), "=f"(hi) : "l"(in))

// ---------------- device scratch (no allocations allowed) ----------------
__device__ __half g_uhat[(size_t)BB * JJ * NN * DD];   // [b][j][n][d], 268 MB
__device__ float  g_v[BB * NN * DD];                   // [b][n][d]
__device__ float  g_blog[(size_t)BB * JJ * NN];        // [b][j][n], 16 MB
__device__ float  g_sp[32 * BB * NN * DD];             // partial s slices, 8 MB

// ---------------- K1: u_hat = einsum('bji,njdi') + partial sum_j u_hat ----------------
// grid = 64 n * 32 superchunks (64 j each), 256 threads. f32x2 packed FMA.
__global__ __launch_bounds__(256) void k1_uhat(const float* __restrict__ x,
                                               const float* __restrict__ W) {
    __shared__ float Ws[8 * 32 * 20];  // [j][d][i pad 20] -> conflict-free LDS.128
    __shared__ float xs[32 * 128];     // [b][(j*16+i)]

    int n  = blockIdx.x >> 5;
    int sc = blockIdx.x & 31;
    int t  = threadIdx.x;
    int w  = t >> 5;      // warp 0..7 -> base b
    int d  = t & 31;      // lane = output dim

    float sacc[4] = {0.f, 0.f, 0.f, 0.f};

    for (int sub = 0; sub < 8; sub++) {
        int j0 = sc * 64 + sub * 8;

        // load W tile: 8 j * 32 d * 16 i = 1024 float4, transposed pad-20
        const float4* Wg = (const float4*)(W + ((size_t)n * JJ + j0) * DD * II);
        #pragma unroll
        for (int r = 0; r < 4; r++) {
            int idx = r * 256 + t;
            float4 v = Wg[idx];
            int q = idx & 3, dd = (idx >> 2) & 31, jj = idx >> 7;
            *(float4*)&Ws[(jj * 32 + dd) * 20 + q * 4] = v;
        }
        // load x tile: 32 b * (8 j * 16 i = 128 contiguous floats)
        #pragma unroll
        for (int r = 0; r < 4; r++) {
            int idx = r * 256 + t;
            int b = idx >> 5, rr = idx & 31;
            const float4* xg = (const float4*)(x + ((size_t)b * JJ + j0) * II);
            *(float4*)&xs[b * 128 + rr * 4] = xg[rr];
        }
        __syncthreads();

        #pragma unroll
        for (int j = 0; j < 8; j++) {
            const float* wrow = &Ws[(j * 32 + d) * 20];
            ulonglong2 w0 = *(const ulonglong2*)(wrow);       // i 0..3  as 2 pairs
            ulonglong2 w1 = *(const ulonglong2*)(wrow + 4);   // i 4..7
            ulonglong2 w2 = *(const ulonglong2*)(wrow + 8);   // i 8..11
            ulonglong2 w3 = *(const ulonglong2*)(wrow + 12);  // i 12..15
            int jg = j0 + j;
            #pragma unroll
            for (int k = 0; k < 4; k++) {
                int b = w + k * 8;
                const float* xrow = &xs[b * 128 + j * 16];    // broadcast across warp
                ulonglong2 x0 = *(const ulonglong2*)(xrow);
                ulonglong2 x1 = *(const ulonglong2*)(xrow + 4);
                ulonglong2 x2 = *(const ulonglong2*)(xrow + 8);
                ulonglong2 x3 = *(const ulonglong2*)(xrow + 12);
                unsigned long long a2 = 0ull;                 // (0.f, 0.f)
                FMA_F32X2(a2, w0.x, x0.x, a2);
                FMA_F32X2(a2, w0.y, x0.y, a2);
                FMA_F32X2(a2, w1.x, x1.x, a2);
                FMA_F32X2(a2, w1.y, x1.y, a2);
                FMA_F32X2(a2, w2.x, x2.x, a2);
                FMA_F32X2(a2, w2.y, x2.y, a2);
                FMA_F32X2(a2, w3.x, x3.x, a2);
                FMA_F32X2(a2, w3.y, x3.y, a2);
                float lo, hi;
                UNPACK_F32X2(lo, hi, a2);
                float acc = lo + hi;
                g_uhat[(((size_t)b * JJ + jg) * NN + n) * DD + d] = __float2half_rn(acc);
                sacc[k] += acc;
            }
        }
        __syncthreads();
    }
    // non-atomic partial: slice sc, value unique per (b,n,d)
    #pragma unroll
    for (int k = 0; k < 4; k++) {
        int b = w + k * 8;
        g_sp[(size_t)sc * (BB * NN * DD) + ((size_t)b * NN + n) * DD + d] = sacc[k];
    }
}

// ---------------- K2: reduce partial slices, squash, write v ----------------
// grid = 256 blocks * 256 threads; warp per (b,n)
__global__ __launch_bounds__(256) void k2_squash(int nslices, float prescale,
                                                 float* __restrict__ outp) {
    int g = blockIdx.x * 8 + (threadIdx.x >> 5);   // 0..2047 = b*64+n
    int l = threadIdx.x & 31;                      // lane = d
    float s = 0.f;
    for (int sl = 0; sl < nslices; sl++)
        s += g_sp[(size_t)sl * (BB * NN * DD) + (size_t)g * DD + l];
    s *= prescale;
    float sq = s * s;
    #pragma unroll
    for (int o = 16; o > 0; o >>= 1) sq += __shfl_xor_sync(0xffffffffu, sq, o);
    float scale = sq / ((1.f + sq) * sqrtf(sq + SQ_EPS));
    float* o = outp ? outp : g_v;
    o[(size_t)g * DD + l] = s * scale;
}

// ---------------- K3: fused routing pass (register-resident u_hat) ----------------
// b_new = b_old + v . u_hat ; c = softmax_n(b_new) ; s_partial += c * u_hat
// grid = 32 b * 16 j-groups (128 j each), 1024 threads.
// Thread t owns (n = t>>4, d-pair = t&15). u tile of 16 j lives in registers.
__global__ __launch_bounds__(1024, 1) void k3_route(int first, int last) {
    __shared__ float lg_s[2][16 * 64];   // logits [buf][j][n]
    __shared__ float c_s[2][16 * 64];    // coupling [buf][j][n]

    int b  = blockIdx.x >> 4;
    int jg = blockIdx.x & 15;
    int t  = threadIdx.x;
    int n  = t >> 4;
    int w  = t >> 5;
    int l  = t & 31;

    // v[b][n][2dp..2dp+1] — coalesced float2
    float2 vv = ((const float2*)g_v)[b * 1024 + t];
    float2 sacc = make_float2(0.f, 0.f);

    for (int sub = 0; sub < 8; sub++) {
        int j0  = jg * 128 + sub * 16;
        int buf = sub & 1;
        const unsigned* ug = (const unsigned*)(g_uhat + ((size_t)b * JJ + j0) * (NN * DD));

        // load 16 j rows; each thread grabs its half2 — 128B/warp coalesced
        unsigned ur[16];
        #pragma unroll
        for (int jj = 0; jj < 16; jj++)
            ur[jj] = ug[jj * 1024 + t];

        // logits: p[j][n] = sum_d v[n][d] * u[j][n][d]   (reduce over 16-lane d-group)
        #pragma unroll
        for (int jj = 0; jj < 16; jj++) {
            float2 uf = __half22float2(*(const __half2*)&ur[jj]);
            float p = fmaf(uf.x, vv.x, uf.y * vv.y);
            #pragma unroll
            for (int o = 8; o > 0; o >>= 1)
                p += __shfl_xor_sync(0xffffffffu, p, o);
            if ((t & 15) == 0) lg_s[buf][jj * 64 + n] = p;
        }
        __syncthreads();

        // softmax over n: warp w (w<16) handles j = j0 + w, 2 n per lane
        if (w < 16) {
            float* bl = &g_blog[((size_t)b * JJ + (j0 + w)) * NN];
            float p0 = lg_s[buf][w * 64 + l];
            float p1 = lg_s[buf][w * 64 + 32 + l];
            if (!first) { p0 += bl[l]; p1 += bl[l + 32]; }
            if (!last)  { bl[l] = p0; bl[l + 32] = p1; }
            float m = fmaxf(p0, p1);
            #pragma unroll
            for (int o = 16; o > 0; o >>= 1)
                m = fmaxf(m, __shfl_xor_sync(0xffffffffu, m, o));
            float e0 = __expf(p0 - m), e1 = __expf(p1 - m);
            float ssum = e0 + e1;
            #pragma unroll
            for (int o = 16; o > 0; o >>= 1)
                ssum += __shfl_xor_sync(0xffffffffu, ssum, o);
            float inv = 1.0f / ssum;
            c_s[buf][w * 64 + l]      = e0 * inv;
            c_s[buf][w * 64 + 32 + l] = e1 * inv;
        }
        __syncthreads();

        // s[n][d] += c[j][n] * u[j][n][d] — u still in registers
        #pragma unroll
        for (int jj = 0; jj < 16; jj++) {
            float c = c_s[buf][jj * 64 + n];   // 2 addrs/warp -> broadcast
            float2 uf = __half22float2(*(const __half2*)&ur[jj]);
            sacc.x = fmaf(c, uf.x, sacc.x);
            sacc.y = fmaf(c, uf.y, sacc.y);
        }
    }

    // non-atomic partial write: slice jg, unique (b,n,d-pair) per thread
    ((float2*)g_sp)[(size_t)jg * (BB * NN * DD / 2) + (size_t)b * 1024 + t] = sacc;
}

// ---------------- launch ----------------
extern "C" void kernel_launch(void* const* d_in, const int* in_sizes, int n_in,
                              void* d_out, int out_size) {
    const float* x = (const float*)d_in[0];
    const float* W = (const float*)d_in[1];
    if (n_in >= 2 && in_sizes[0] != BB * JJ * II) {   // defend against input ordering
        x = (const float*)d_in[1];
        W = (const float*)d_in[0];
    }
    float* out = (float*)d_out;

    k1_uhat<<<2048, 256>>>(x, W);                      // u_hat (fp16) + raw sum_j partials
    k2_squash<<<256, 256>>>(32, 1.0f / NN, nullptr);   // v0 = squash(sum/64)
    k3_route<<<512, 1024>>>(1, 0);                     // b1, c1, s1 partials (b_old = 0)
    k2_squash<<<256, 256>>>(16, 1.0f, nullptr);        // v1
    k3_route<<<512, 1024>>>(0, 1);                     // b2, c2, s2 partials
    k2_squash<<<256, 256>>>(16, 1.0f, out);            // v2 -> output
}

// round 4
// speedup vs baseline: 1.5089x; 1.1930x over previous
#include <cuda_runtime.h>
#include <cuda_fp16.h>

#define BB 32
#define JJ 2048
#define II 16
#define NN 64
#define DD 32
#define SQ_EPS 1e-7f

// packed 2-wide fp32 FMA (sm_103a; only reachable via PTX)
#define FMA_F32X2(d, a, b, c) \
    asm("fma.rn.f32x2 %0, %1, %2, %3;" : "=l"(d) : "l"(a), "l"(b), "l"(c))
#define UNPACK_F32X2(lo, hi, in) \
    asm("mov.b64 {%0, %1}, %2;" : "=f"(lo), "=f"(hi) : "l"(in))

// ---------------- device scratch (no allocations allowed) ----------------
__device__ __half g_uhat[(size_t)BB * JJ * NN * DD];   // [b][j][n][d], 268 MB
__device__ float  g_v[BB * NN * DD];                   // [b][n][d]
__device__ float  g_blog[(size_t)BB * JJ * NN];        // [b][j][n], 16 MB
__device__ float  g_sp[64 * BB * NN * DD];             // partial s slices, 16 MB

// ---------------- dummy (aligns ncu's -s 5 -c 1 onto k1) ----------------
__global__ void k_nop() {}

// ---------------- K1: u_hat = einsum('bji,njdi') + partial sum_j u_hat ----------------
// grid = 32 n-pairs * 32 j-chunks (64 j each), 256 threads (8 warps).
// warp w: b-group = w&3 (8 b), j-slot = w>>2 (4 j per sub). lane = d.
// W rows live in registers per j; x via broadcast LDS; s-partials in registers.
#define K1_SMEM ((2 * 8 * 32 * 20 + 32 * 128) * 4)   // Ws 40KB + xs 16KB = 57344 B

__global__ __launch_bounds__(256) void k1_uhat(const float* __restrict__ x,
                                               const float* __restrict__ W) {
    extern __shared__ float sm1[];
    float* Ws = sm1;                    // [n2][jl][d] rows of 16, padded stride 20
    float* xs = sm1 + 2 * 8 * 32 * 20;  // [b][jl*16+i]

    int np = blockIdx.x >> 5;        // n-pair
    int jc = blockIdx.x & 31;        // j-chunk (64 j)
    int t  = threadIdx.x;
    int w  = t >> 5;
    int lane = t & 31;               // d
    int bg = w & 3;                  // b-group: b in [8bg, 8bg+8)
    int js = w >> 2;                 // j-slot: jl in [4js, 4js+4)

    float sacc[2][8];
    #pragma unroll
    for (int nn = 0; nn < 2; nn++)
        #pragma unroll
        for (int bb = 0; bb < 8; bb++) sacc[nn][bb] = 0.f;

    for (int sub = 0; sub < 8; sub++) {
        int j0 = jc * 64 + sub * 8;
        __syncthreads();

        // stage W: 2n * 8j * 32d * 16i = 2048 float4, 8 per thread, transpose pad-20
        const float4* W4 = (const float4*)W;
        #pragma unroll
        for (int r = 0; r < 8; r++) {
            int idx = r * 256 + t;
            int n_l = idx >> 10, rem = idx & 1023;
            int jl = rem >> 7, d = (rem >> 2) & 31, q = rem & 3;
            float4 v = W4[(((np * 2 + n_l) * JJ + (j0 + jl)) << 7) + d * 4 + q];
            *(float4*)&Ws[((n_l * 8 + jl) * 32 + d) * 20 + q * 4] = v;
        }
        // stage x: 32 b * 128 floats = 1024 float4, 4 per thread
        #pragma unroll
        for (int r = 0; r < 4; r++) {
            int idx = r * 256 + t;
            int b = idx >> 5, rr = idx & 31;
            *(float4*)&xs[b * 128 + rr * 4] =
                ((const float4*)x)[(b * JJ + j0) * 4 + rr];
        }
        __syncthreads();

        #pragma unroll
        for (int jj = 0; jj < 4; jj++) {
            int jl = js * 4 + jj;
            int jglob = j0 + jl;
            // W rows (2 n) for this (j, d=lane) -> registers (all 16 i!)
            ulonglong2 wr[2][4];
            #pragma unroll
            for (int nn = 0; nn < 2; nn++) {
                const float* row = &Ws[((nn * 8 + jl) * 32 + lane) * 20];
                wr[nn][0] = *(const ulonglong2*)(row);       // i 0..3
                wr[nn][1] = *(const ulonglong2*)(row + 4);   // i 4..7
                wr[nn][2] = *(const ulonglong2*)(row + 8);   // i 8..11
                wr[nn][3] = *(const ulonglong2*)(row + 12);  // i 12..15
            }
            #pragma unroll
            for (int bb = 0; bb < 8; bb++) {
                int b = bg * 8 + bb;
                const float* xrow = &xs[b * 128 + jl * 16];   // broadcast
                ulonglong2 x0 = *(const ulonglong2*)(xrow);
                ulonglong2 x1 = *(const ulonglong2*)(xrow + 4);
                ulonglong2 x2 = *(const ulonglong2*)(xrow + 8);
                ulonglong2 x3 = *(const ulonglong2*)(xrow + 12);
                #pragma unroll
                for (int nn = 0; nn < 2; nn++) {
                    unsigned long long a2 = 0ull;
                    FMA_F32X2(a2, wr[nn][0].x, x0.x, a2);
                    FMA_F32X2(a2, wr[nn][0].y, x0.y, a2);
                    FMA_F32X2(a2, wr[nn][1].x, x1.x, a2);
                    FMA_F32X2(a2, wr[nn][1].y, x1.y, a2);
                    FMA_F32X2(a2, wr[nn][2].x, x2.x, a2);
                    FMA_F32X2(a2, wr[nn][2].y, x2.y, a2);
                    FMA_F32X2(a2, wr[nn][3].x, x3.x, a2);
                    FMA_F32X2(a2, wr[nn][3].y, x3.y, a2);
                    float lo, hi;
                    UNPACK_F32X2(lo, hi, a2);
                    float acc = lo + hi;
                    sacc[nn][bb] += acc;
                    g_uhat[((b * JJ + jglob) * NN + (np * 2 + nn)) * DD + lane] =
                        __float2half_rn(acc);
                }
            }
        }
    }

    // flush register partials: slice = jc*2 + js  (64 slices)
    int slice = jc * 2 + js;
    #pragma unroll
    for (int nn = 0; nn < 2; nn++)
        #pragma unroll
        for (int bb = 0; bb < 8; bb++)
            g_sp[(size_t)slice * (BB * NN * DD) +
                 ((bg * 8 + bb) * NN + np * 2 + nn) * DD + lane] = sacc[nn][bb];
}

// ---------------- K2: reduce partial slices, squash, write v ----------------
__global__ __launch_bounds__(256) void k2_squash(int nslices, float prescale,
                                                 float* __restrict__ outp) {
    int g = blockIdx.x * 8 + (threadIdx.x >> 5);   // 0..2047 = b*64+n
    int l = threadIdx.x & 31;                      // lane = d
    float s = 0.f;
    for (int sl = 0; sl < nslices; sl++)
        s += g_sp[(size_t)sl * (BB * NN * DD) + (size_t)g * DD + l];
    s *= prescale;
    float sq = s * s;
    #pragma unroll
    for (int o = 16; o > 0; o >>= 1) sq += __shfl_xor_sync(0xffffffffu, sq, o);
    float scale = sq / ((1.f + sq) * sqrtf(sq + SQ_EPS));
    float* o = outp ? outp : g_v;
    o[(size_t)g * DD + l] = s * scale;
}

// ---------------- K3: fused routing pass (register-resident u_hat) ----------------
__global__ __launch_bounds__(1024, 1) void k3_route(int first, int last) {
    __shared__ float lg_s[2][16 * 64];   // logits [buf][j][n]
    __shared__ float c_s[2][16 * 64];    // coupling [buf][j][n]

    int b  = blockIdx.x >> 4;
    int jg = blockIdx.x & 15;
    int t  = threadIdx.x;
    int n  = t >> 4;
    int w  = t >> 5;
    int l  = t & 31;

    float2 vv = ((const float2*)g_v)[b * 1024 + t];
    float2 sacc = make_float2(0.f, 0.f);

    for (int sub = 0; sub < 8; sub++) {
        int j0  = jg * 128 + sub * 16;
        int buf = sub & 1;
        const unsigned* ug = (const unsigned*)(g_uhat + ((size_t)b * JJ + j0) * (NN * DD));

        unsigned ur[16];
        #pragma unroll
        for (int jj = 0; jj < 16; jj++)
            ur[jj] = ug[jj * 1024 + t];

        #pragma unroll
        for (int jj = 0; jj < 16; jj++) {
            float2 uf = __half22float2(*(const __half2*)&ur[jj]);
            float p = fmaf(uf.x, vv.x, uf.y * vv.y);
            #pragma unroll
            for (int o = 8; o > 0; o >>= 1)
                p += __shfl_xor_sync(0xffffffffu, p, o);
            if ((t & 15) == 0) lg_s[buf][jj * 64 + n] = p;
        }
        __syncthreads();

        if (w < 16) {
            float* bl = &g_blog[((size_t)b * JJ + (j0 + w)) * NN];
            float p0 = lg_s[buf][w * 64 + l];
            float p1 = lg_s[buf][w * 64 + 32 + l];
            if (!first) { p0 += bl[l]; p1 += bl[l + 32]; }
            if (!last)  { bl[l] = p0; bl[l + 32] = p1; }
            float m = fmaxf(p0, p1);
            #pragma unroll
            for (int o = 16; o > 0; o >>= 1)
                m = fmaxf(m, __shfl_xor_sync(0xffffffffu, m, o));
            float e0 = __expf(p0 - m), e1 = __expf(p1 - m);
            float ssum = e0 + e1;
            #pragma unroll
            for (int o = 16; o > 0; o >>= 1)
                ssum += __shfl_xor_sync(0xffffffffu, ssum, o);
            float inv = 1.0f / ssum;
            c_s[buf][w * 64 + l]      = e0 * inv;
            c_s[buf][w * 64 + 32 + l] = e1 * inv;
        }
        __syncthreads();

        #pragma unroll
        for (int jj = 0; jj < 16; jj++) {
            float c = c_s[buf][jj * 64 + n];
            float2 uf = __half22float2(*(const __half2*)&ur[jj]);
            sacc.x = fmaf(c, uf.x, sacc.x);
            sacc.y = fmaf(c, uf.y, sacc.y);
        }
    }

    ((float2*)g_sp)[(size_t)jg * (BB * NN * DD / 2) + (size_t)b * 1024 + t] = sacc;
}

// ---------------- launch ----------------
extern "C" void kernel_launch(void* const* d_in, const int* in_sizes, int n_in,
                              void* d_out, int out_size) {
    const float* x = (const float*)d_in[0];
    const float* W = (const float*)d_in[1];
    if (n_in >= 2 && in_sizes[0] != BB * JJ * II) {
        x = (const float*)d_in[1];
        W = (const float*)d_in[0];
    }
    float* out = (float*)d_out;

    cudaFuncSetAttribute(k1_uhat, cudaFuncAttributeMaxDynamicSharedMemorySize, K1_SMEM);

    // 5 no-op launches so ncu's "-s 5 -c 1" captures k1 (launch #6)
    k_nop<<<1, 32>>>(); k_nop<<<1, 32>>>(); k_nop<<<1, 32>>>();
    k_nop<<<1, 32>>>(); k_nop<<<1, 32>>>();

    k1_uhat<<<1024, 256, K1_SMEM>>>(x, W);             // u_hat (fp16) + 64 s-partial slices
    k2_squash<<<256, 256>>>(64, 1.0f / NN, nullptr);   // v0 = squash(sum/64)
    k3_route<<<512, 1024>>>(1, 0);                     // b1, c1, s1 partials (b_old = 0)
    k2_squash<<<256, 256>>>(16, 1.0f, nullptr);        // v1
    k3_route<<<512, 1024>>>(0, 1);                     // b2, c2, s2 partials
    k2_squash<<<256, 256>>>(16, 1.0f, out);            // v2 -> output
}